// round 4
// baseline (speedup 1.0000x reference)
#include <cuda_runtime.h>

// Attn_Pred_Model: out[slice][s][b] =
//   ( sum_{i=0..7} alpha*beta^i * x[slice][s-1-i][b] + pb_fwd[b]
//     + pb_bwd[((s>>6)-b) & 63] ) * mask(s,b)
// mask(s,b) = 1 iff s >= max(128, 64*(b+1))  (band-constant, band = 64 rows)
//
// Traffic: ~130MB predicated reads (triangle-dead x skipped per-lane) +
// 256MB mandatory writes. R3 change: CHUNK 256->128 doubles grid to 2048
// blocks; previous config was grid-limited (6.9 blocks/SM < 9 reg-limit),
// capping occupancy at 38% and DRAM at 70%.

#define S_DIM   4096
#define B_DIM   64
#define SLICES  256
#define PAST    8
#define CHUNK   128              // rows per thread
#define N_CHUNK (S_DIM / CHUNK)  // 32

__global__ __launch_bounds__(128)
void attn_pred_kernel(const float* __restrict__ x,
                      const float* __restrict__ pb_fwd,
                      const float* __restrict__ pb_bwd,
                      const float* __restrict__ alpha_p,
                      const float* __restrict__ beta_p,
                      float* __restrict__ out)
{
    const int t     = blockIdx.x * blockDim.x + threadIdx.x;
    const int tb    = t & 31;        // float2 lane: columns b0=2*tb, b1=2*tb+1
    const int rest  = t >> 5;
    const int chunk = rest & (N_CHUNK - 1);
    const int slice = rest >> 5;     // rest / N_CHUNK

    // decay coefficients c[i] = alpha * beta^i
    const float alpha = alpha_p[0];
    const float beta  = beta_p[0];
    float c[PAST];
    {
        float cv = alpha;
        #pragma unroll
        for (int i = 0; i < PAST; i++) { c[i] = cv; cv *= beta; }
    }

    const int b0 = 2 * tb;
    const int b1 = b0 + 1;
    const float pf0 = __ldg(&pb_fwd[b0]);
    const float pf1 = __ldg(&pb_fwd[b1]);

    // first active band per column: active iff s >= 64*qact
    const int qact0 = (b0 + 1 < 2) ? 2 : (b0 + 1);   // max(2, b0+1)
    const int qact1 = b1 + 1;                        // b1 >= 1 so already >= 2
    // load needed iff s + 8 >= 64*qact0  (x[s] feeds out[s+1..s+8]; col b1
    // activates later than b0, so b0's predicate covers the float2 pair)
    const int ld_thresh = (qact0 << 6) - 8;

    const size_t slice_off = (size_t)slice * S_DIM * (B_DIM / 2); // float2 units
    const float2* __restrict__ xin  = (const float2*)x  + slice_off + tb;
    float2*       __restrict__ xout = (float2*)out      + slice_off + tb;

    const int s0 = chunk * CHUNK;

    // rolling window: w[i] = x[s-1-i] for current s (= s0 at start)
    float2 w[PAST];
    #pragma unroll
    for (int i = 0; i < PAST; i++) {
        const int sr = s0 - 1 - i;
        w[i] = (sr >= 0 && sr >= ld_thresh) ? xin[(size_t)sr * 32]
                                            : make_float2(0.f, 0.f);
    }

    #pragma unroll
    for (int band = 0; band < CHUNK / 64; band++) {
        const int q = (s0 >> 6) + band;          // bucket row index, constant in band
        const float bias0 = pf0 + __ldg(&pb_bwd[(q - b0) & 63]);
        const float bias1 = pf1 + __ldg(&pb_bwd[(q - b1) & 63]);
        const float m0 = (q >= qact0) ? 1.f : 0.f;
        const float m1 = (q >= qact1) ? 1.f : 0.f;
        const int sbase = q * 64;

        #pragma unroll 8   // depth == PAST so window shift is free register rotation
        for (int r = 0; r < 64; r++) {
            const int s = sbase + r;
            // predicated load: skipped lanes fetch nothing from DRAM
            const float2 cur = (s >= ld_thresh) ? xin[(size_t)s * 32]
                                                : make_float2(0.f, 0.f);

            float ax = 0.f, ay = 0.f;
            #pragma unroll
            for (int i = 0; i < PAST; i++) {
                ax = fmaf(c[i], w[i].x, ax);
                ay = fmaf(c[i], w[i].y, ay);
            }

            float2 o;
            o.x = m0 * (ax + bias0);
            o.y = m1 * (ay + bias1);
            xout[(size_t)s * 32] = o;

            #pragma unroll
            for (int i = PAST - 1; i > 0; i--) w[i] = w[i - 1];
            w[0] = cur;
        }
    }
}

extern "C" void kernel_launch(void* const* d_in, const int* in_sizes, int n_in,
                              void* d_out, int out_size)
{
    // metadata order: x, pb_fwd, pb_bwd, alpha, beta, arange2, mask
    const float* x      = (const float*)d_in[0];
    const float* pb_fwd = (const float*)d_in[1];
    const float* pb_bwd = (const float*)d_in[2];
    const float* alpha  = (const float*)d_in[3];
    const float* beta   = (const float*)d_in[4];
    // arange2 (d_in[5]) and mask (d_in[6]) are reproduced analytically in-kernel.

    const int total_threads = SLICES * N_CHUNK * 32;  // 262144
    const int block = 128;
    attn_pred_kernel<<<total_threads / block, block>>>(
        x, pb_fwd, pb_bwd, alpha, beta, (float*)d_out);
}

// round 6
// speedup vs baseline: 1.1000x; 1.1000x over previous
#include <cuda_runtime.h>

// Attn_Pred_Model: out[slice][s][b] =
//   ( sum_{i=0..7} alpha*beta^i * x[slice][s-1-i][b] + pb_fwd[b]
//     + pb_bwd[((s>>6)-b) & 63] ) * mask(s,b)
// mask(s,b) = 1 iff s >= max(128, 64*(b+1))  (band-constant, band = 64 rows)
//
// R4: revert to single-wave geometry (CHUNK=256, grid=1024: 4096 warp-tasks
// <= 5328 resident warp slots -> one full-residency wave; R3's 2048-block
// config produced a 0.54 partial second wave and regressed).
// Adds: streaming cache hints (__ldcs/__stcs, each byte touched once) and
// explicit 8-row load batching (guaranteed MLP=8 front-batched LDGs).
// Reads ~140MB (triangle-dead x predicated off per-lane), writes 256MB.

#define S_DIM   4096
#define B_DIM   64
#define SLICES  256
#define PAST    8
#define CHUNK   256              // rows per thread
#define N_CHUNK (S_DIM / CHUNK)  // 16

__global__ __launch_bounds__(128)
void attn_pred_kernel(const float* __restrict__ x,
                      const float* __restrict__ pb_fwd,
                      const float* __restrict__ pb_bwd,
                      const float* __restrict__ alpha_p,
                      const float* __restrict__ beta_p,
                      float* __restrict__ out)
{
    const int t     = blockIdx.x * blockDim.x + threadIdx.x;
    const int tb    = t & 31;        // float2 lane: columns b0=2*tb, b1=2*tb+1
    const int rest  = t >> 5;
    const int chunk = rest & (N_CHUNK - 1);
    const int slice = rest >> 4;     // rest / N_CHUNK

    // decay coefficients c[i] = alpha * beta^i
    const float alpha = alpha_p[0];
    const float beta  = beta_p[0];
    float c[PAST];
    {
        float cv = alpha;
        #pragma unroll
        for (int i = 0; i < PAST; i++) { c[i] = cv; cv *= beta; }
    }

    const int b0 = 2 * tb;
    const int b1 = b0 + 1;
    const float pf0 = __ldg(&pb_fwd[b0]);
    const float pf1 = __ldg(&pb_fwd[b1]);

    // first active band per column: active iff s >= 64*qact
    const int qact0 = (b0 + 1 < 2) ? 2 : (b0 + 1);   // max(2, b0+1)
    const int qact1 = b1 + 1;                        // b1 >= 1 so already >= 2
    // load needed iff s + 8 >= 64*qact0  (x[s] feeds out[s+1..s+8]; col b1
    // activates later than b0, so b0's predicate covers the float2 pair)
    const int ld_thresh = (qact0 << 6) - 8;

    const size_t slice_off = (size_t)slice * S_DIM * (B_DIM / 2); // float2 units
    const float2* __restrict__ xin  = (const float2*)x  + slice_off + tb;
    float2*       __restrict__ xout = (float2*)out      + slice_off + tb;

    const int s0 = chunk * CHUNK;

    // rolling window: w[i] = x[s-1-i] for current s (= s0 at start)
    float2 w[PAST];
    #pragma unroll
    for (int i = 0; i < PAST; i++) {
        const int sr = s0 - 1 - i;
        w[i] = (sr >= 0 && sr >= ld_thresh) ? __ldcs(&xin[(size_t)sr * 32])
                                            : make_float2(0.f, 0.f);
    }

    #pragma unroll
    for (int band = 0; band < CHUNK / 64; band++) {
        const int q = (s0 >> 6) + band;          // bucket row index, constant in band
        const float bias0 = pf0 + __ldg(&pb_bwd[(q - b0) & 63]);
        const float bias1 = pf1 + __ldg(&pb_bwd[(q - b1) & 63]);
        const float m0 = (q >= qact0) ? 1.f : 0.f;
        const float m1 = (q >= qact1) ? 1.f : 0.f;
        const int sbase = q * 64;

        // 8 groups of 8 rows: batch-load 8 rows (MLP=8), then compute/store.
        for (int rg = 0; rg < 8; rg++) {
            const int sg = sbase + rg * 8;

            float2 v[PAST];
            #pragma unroll
            for (int k = 0; k < PAST; k++) {
                const int s = sg + k;
                v[k] = (s >= ld_thresh) ? __ldcs(&xin[(size_t)s * 32])
                                        : make_float2(0.f, 0.f);
            }

            #pragma unroll
            for (int k = 0; k < PAST; k++) {
                float ax = 0.f, ay = 0.f;
                #pragma unroll
                for (int i = 0; i < PAST; i++) {
                    ax = fmaf(c[i], w[i].x, ax);
                    ay = fmaf(c[i], w[i].y, ay);
                }

                float2 o;
                o.x = m0 * (ax + bias0);
                o.y = m1 * (ay + bias1);
                __stcs(&xout[(size_t)(sg + k) * 32], o);

                #pragma unroll
                for (int i = PAST - 1; i > 0; i--) w[i] = w[i - 1];
                w[0] = v[k];
            }
        }
    }
}

extern "C" void kernel_launch(void* const* d_in, const int* in_sizes, int n_in,
                              void* d_out, int out_size)
{
    // metadata order: x, pb_fwd, pb_bwd, alpha, beta, arange2, mask
    const float* x      = (const float*)d_in[0];
    const float* pb_fwd = (const float*)d_in[1];
    const float* pb_bwd = (const float*)d_in[2];
    const float* alpha  = (const float*)d_in[3];
    const float* beta   = (const float*)d_in[4];
    // arange2 (d_in[5]) and mask (d_in[6]) are reproduced analytically in-kernel.

    const int total_threads = SLICES * N_CHUNK * 32;  // 131072
    const int block = 128;
    attn_pred_kernel<<<total_threads / block, block>>>(
        x, pb_fwd, pb_bwd, alpha, beta, (float*)d_out);
}

// round 8
// speedup vs baseline: 1.1561x; 1.0510x over previous
#include <cuda_runtime.h>

// Attn_Pred_Model: out[slice][s][b] =
//   ( sum_{i=0..7} alpha*beta^i * x[slice][s-1-i][b] + pb_fwd[b]
//     + pb_bwd[((s>>6)-b) & 63] ) * mask(s,b)
// mask(s,b) = 1 iff s >= max(128, 64*(b+1))  (band-constant, band = 64 rows)
//
// Confirmed-best configuration (R2): CHUNK=256 / grid=1024 single-wave
// geometry, per-lane predicated loads skipping the mask-dead triangle
// (~49% of reads), plain LDG/STG (streaming cache hints measured -2%:
// R4), implicit ptxas scheduling of the fused load/FMA/store body
// (explicit 8-row batching measured neutral-to-negative).
// Kernel is at the mixed R/W stream throughput ceiling (~5.6-5.9 TB/s),
// not latency- or occupancy-limited.

#define S_DIM   4096
#define B_DIM   64
#define SLICES  256
#define PAST    8
#define CHUNK   256              // rows per thread
#define N_CHUNK (S_DIM / CHUNK)  // 16

__global__ __launch_bounds__(128)
void attn_pred_kernel(const float* __restrict__ x,
                      const float* __restrict__ pb_fwd,
                      const float* __restrict__ pb_bwd,
                      const float* __restrict__ alpha_p,
                      const float* __restrict__ beta_p,
                      float* __restrict__ out)
{
    const int t     = blockIdx.x * blockDim.x + threadIdx.x;
    const int tb    = t & 31;        // float2 lane: columns b0=2*tb, b1=2*tb+1
    const int rest  = t >> 5;
    const int chunk = rest & (N_CHUNK - 1);
    const int slice = rest >> 4;     // rest / N_CHUNK

    // decay coefficients c[i] = alpha * beta^i
    const float alpha = alpha_p[0];
    const float beta  = beta_p[0];
    float c[PAST];
    {
        float cv = alpha;
        #pragma unroll
        for (int i = 0; i < PAST; i++) { c[i] = cv; cv *= beta; }
    }

    const int b0 = 2 * tb;
    const int b1 = b0 + 1;
    const float pf0 = __ldg(&pb_fwd[b0]);
    const float pf1 = __ldg(&pb_fwd[b1]);

    // first active band per column: active iff s >= 64*qact
    const int qact0 = (b0 + 1 < 2) ? 2 : (b0 + 1);   // max(2, b0+1)
    const int qact1 = b1 + 1;                        // b1 >= 1 so already >= 2
    // load needed iff s + 8 >= 64*qact0  (x[s] feeds out[s+1..s+8]; col b1
    // activates later than b0, so b0's predicate covers the float2 pair)
    const int ld_thresh = (qact0 << 6) - 8;

    const size_t slice_off = (size_t)slice * S_DIM * (B_DIM / 2); // float2 units
    const float2* __restrict__ xin  = (const float2*)x  + slice_off + tb;
    float2*       __restrict__ xout = (float2*)out      + slice_off + tb;

    const int s0 = chunk * CHUNK;

    // rolling window: w[i] = x[s-1-i] for current s (= s0 at start)
    float2 w[PAST];
    #pragma unroll
    for (int i = 0; i < PAST; i++) {
        const int sr = s0 - 1 - i;
        w[i] = (sr >= 0 && sr >= ld_thresh) ? xin[(size_t)sr * 32]
                                            : make_float2(0.f, 0.f);
    }

    #pragma unroll
    for (int band = 0; band < CHUNK / 64; band++) {
        const int q = (s0 >> 6) + band;          // bucket row index, constant in band
        const float bias0 = pf0 + __ldg(&pb_bwd[(q - b0) & 63]);
        const float bias1 = pf1 + __ldg(&pb_bwd[(q - b1) & 63]);
        const float m0 = (q >= qact0) ? 1.f : 0.f;
        const float m1 = (q >= qact1) ? 1.f : 0.f;
        const int sbase = q * 64;

        #pragma unroll 8   // depth == PAST so window shift is free register rotation
        for (int r = 0; r < 64; r++) {
            const int s = sbase + r;
            // predicated load: skipped lanes fetch nothing from DRAM
            const float2 cur = (s >= ld_thresh) ? xin[(size_t)s * 32]
                                                : make_float2(0.f, 0.f);

            float ax = 0.f, ay = 0.f;
            #pragma unroll
            for (int i = 0; i < PAST; i++) {
                ax = fmaf(c[i], w[i].x, ax);
                ay = fmaf(c[i], w[i].y, ay);
            }

            float2 o;
            o.x = m0 * (ax + bias0);
            o.y = m1 * (ay + bias1);
            xout[(size_t)s * 32] = o;

            #pragma unroll
            for (int i = PAST - 1; i > 0; i--) w[i] = w[i - 1];
            w[0] = cur;
        }
    }
}

extern "C" void kernel_launch(void* const* d_in, const int* in_sizes, int n_in,
                              void* d_out, int out_size)
{
    // metadata order: x, pb_fwd, pb_bwd, alpha, beta, arange2, mask
    const float* x      = (const float*)d_in[0];
    const float* pb_fwd = (const float*)d_in[1];
    const float* pb_bwd = (const float*)d_in[2];
    const float* alpha  = (const float*)d_in[3];
    const float* beta   = (const float*)d_in[4];
    // arange2 (d_in[5]) and mask (d_in[6]) are reproduced analytically in-kernel.

    const int total_threads = SLICES * N_CHUNK * 32;  // 131072
    const int block = 128;
    attn_pred_kernel<<<total_threads / block, block>>>(
        x, pb_fwd, pb_bwd, alpha, beta, (float*)d_out);
}